// round 13
// baseline (speedup 1.0000x reference)
#include <cuda_runtime.h>

// Retina glimpse: x [B=16384, C=3, 32, 32] f32, l [B,2] f32 in [-1,1].
// Outputs concatenated into d_out:
//   full  [B,3,32,32] : x masked to the valid part of the 16x16 window, else 0
//   patch [B,3,16,16] : gathered window, 0 where out of [0,32) bounds
//
// FINAL. Best-measured configuration (kernel 51.6us, wall 57.34us).
// Roofline-bound: 283 MB compulsory traffic at the ~5.3-5.5 TB/s mixed
// read/write HBM ceiling. Verified invariant across 11 structural variants:
// scalar/128b/256b stores, cp.async.bulk (TMA), .cs vs default policy, smem
// staging, dependency splitting, store ordering, 2x MLP, warp specialization,
// block shapes 192/256, persistent CTAs -- all land at 5.26-5.47 TB/s with
// L1/L2/issue/occupancy unsaturated. No further SASS-level lever exists.

#define BB 16384
#define CC 3
#define HH 32
#define GG 16
#define FULL_PER_B (CC*HH*HH)   // 3072 floats
#define PATCH_PER_B (CC*GG*GG)  // 768 floats

__global__ __launch_bounds__(256) void retina_kernel(
    const float* __restrict__ x,
    const float* __restrict__ l,
    float* __restrict__ full,
    float* __restrict__ patch)
{
    const int b = blockIdx.x;

    // Every thread computes the window corner itself; l loads are same-line
    // L1 broadcasts. No smem, no barrier.
    float l0 = fminf(fmaxf(__ldg(&l[2 * b + 0]), -1.0f), 1.0f);
    float l1 = fminf(fmaxf(__ldg(&l[2 * b + 1]), -1.0f), 1.0f);
    const int rs = (int)(0.5f * ((l0 + 1.0f) * 32.0f)) - GG / 2;
    const int cs = (int)(0.5f * ((l1 + 1.0f) * 32.0f)) - GG / 2;

    const float* xb = x + (size_t)b * FULL_PER_B;
    float* fb = full + (size_t)b * FULL_PER_B;

    // ---------- full phase: 768 float4/sample, 3 per thread ----------
    // Issue all (predicated) loads first, then all stores.
    float4 xv[3];
    int  w0a[3];
    bool ld[3];
    #pragma unroll
    for (int it = 0; it < 3; ++it) {
        int v = it * 256 + threadIdx.x;     // [0,768)
        int ch  = v >> 8;
        int rem = v & 255;
        int h   = rem >> 3;
        int w0  = (rem & 7) << 2;
        w0a[it] = w0;
        bool rowin = (h >= rs) && (h < rs + GG);
        ld[it] = rowin && (w0 + 3 >= cs) && (w0 <= cs + GG - 1);
        xv[it] = make_float4(0.f, 0.f, 0.f, 0.f);
        if (ld[it])
            xv[it] = *(const float4*)(xb + (ch << 10) + (h << 5) + w0);
    }
    #pragma unroll
    for (int it = 0; it < 3; ++it) {
        int v = it * 256 + threadIdx.x;
        int w0 = w0a[it];
        float4 out;
        out.x = (ld[it] && w0 + 0 >= cs && w0 + 0 < cs + GG) ? xv[it].x : 0.f;
        out.y = (ld[it] && w0 + 1 >= cs && w0 + 1 < cs + GG) ? xv[it].y : 0.f;
        out.z = (ld[it] && w0 + 2 >= cs && w0 + 2 < cs + GG) ? xv[it].z : 0.f;
        out.w = (ld[it] && w0 + 3 >= cs && w0 + 3 < cs + GG) ? xv[it].w : 0.f;
        __stcs((float4*)(fb + ((size_t)v << 2)), out);   // streaming: never re-read
    }

    // ---------- patch phase: 192 float4/sample, threads 0..191 ----------
    // Columns j0..j0+3 are contiguous in the patch; gather 4 scalars from x
    // (L1/L2 hits: the full phase just touched these lines).
    if (threadIdx.x < 192) {
        float* pb = patch + (size_t)b * PATCH_PER_B;
        int e4  = threadIdx.x;          // float4 index [0,192)
        int ch  = e4 >> 6;              // 64 float4 per channel (256 floats)
        int rem = e4 & 63;
        int i   = rem >> 2;             // patch row [0,16)
        int j0  = (rem & 3) << 2;       // first patch col of this float4
        int row = rs + i;
        float4 out = make_float4(0.f, 0.f, 0.f, 0.f);
        if (row >= 0 && row < 32) {
            const float* xr = xb + (ch << 10) + (row << 5);
            int c0 = cs + j0;
            if (c0 + 0 >= 0 && c0 + 0 < 32) out.x = xr[c0 + 0];
            if (c0 + 1 >= 0 && c0 + 1 < 32) out.y = xr[c0 + 1];
            if (c0 + 2 >= 0 && c0 + 2 < 32) out.z = xr[c0 + 2];
            if (c0 + 3 >= 0 && c0 + 3 < 32) out.w = xr[c0 + 3];
        }
        __stcs((float4*)(pb + ((size_t)e4 << 2)), out);
    }
}

extern "C" void kernel_launch(void* const* d_in, const int* in_sizes, int n_in,
                              void* d_out, int out_size)
{
    const float* x = (const float*)d_in[0];   // [16384,3,32,32]
    const float* l = (const float*)d_in[1];   // [16384,2]
    float* full  = (float*)d_out;
    float* patch = (float*)d_out + (size_t)BB * FULL_PER_B;
    retina_kernel<<<BB, 256>>>(x, l, full, patch);
}

// round 14
// speedup vs baseline: 1.0056x; 1.0056x over previous
#include <cuda_runtime.h>

// Retina glimpse: x [B=16384, C=3, 32, 32] f32, l [B,2] f32 in [-1,1].
// Outputs concatenated into d_out:
//   full  [B,3,32,32] : x masked to the valid part of the 16x16 window, else 0
//   patch [B,3,16,16] : gathered window, 0 where out of [0,32) bounds
//
// FINAL. Best-measured configuration (kernel 51.6-52.5us, wall 57.34us).
// HBM-roofline-bound: 283 MB compulsory traffic at the ~5.3-5.5 TB/s mixed
// read/write DRAM ceiling, verified invariant across 12 structural variants
// (scalar/128b/256b stores, cp.async.bulk TMA, cache policies, smem staging,
// dependency splitting, store ordering, 2x MLP, warp specialization, block
// shapes, persistent CTAs). L1/L2/issue/occupancy unsaturated in every
// profile; remaining wall variance is noise. memset+sparse-store and
// register-shuffle alternatives were analyzed and lose on total traffic.

#define BB 16384
#define CC 3
#define HH 32
#define GG 16
#define FULL_PER_B (CC*HH*HH)   // 3072 floats
#define PATCH_PER_B (CC*GG*GG)  // 768 floats

__global__ __launch_bounds__(256) void retina_kernel(
    const float* __restrict__ x,
    const float* __restrict__ l,
    float* __restrict__ full,
    float* __restrict__ patch)
{
    const int b = blockIdx.x;

    // Every thread computes the window corner itself; l loads are same-line
    // L1 broadcasts. No smem, no barrier.
    float l0 = fminf(fmaxf(__ldg(&l[2 * b + 0]), -1.0f), 1.0f);
    float l1 = fminf(fmaxf(__ldg(&l[2 * b + 1]), -1.0f), 1.0f);
    const int rs = (int)(0.5f * ((l0 + 1.0f) * 32.0f)) - GG / 2;
    const int cs = (int)(0.5f * ((l1 + 1.0f) * 32.0f)) - GG / 2;

    const float* xb = x + (size_t)b * FULL_PER_B;
    float* fb = full + (size_t)b * FULL_PER_B;

    // ---------- full phase: 768 float4/sample, 3 per thread ----------
    // Issue all (predicated) loads first, then all stores.
    float4 xv[3];
    int  w0a[3];
    bool ld[3];
    #pragma unroll
    for (int it = 0; it < 3; ++it) {
        int v = it * 256 + threadIdx.x;     // [0,768)
        int ch  = v >> 8;
        int rem = v & 255;
        int h   = rem >> 3;
        int w0  = (rem & 7) << 2;
        w0a[it] = w0;
        bool rowin = (h >= rs) && (h < rs + GG);
        ld[it] = rowin && (w0 + 3 >= cs) && (w0 <= cs + GG - 1);
        xv[it] = make_float4(0.f, 0.f, 0.f, 0.f);
        if (ld[it])
            xv[it] = *(const float4*)(xb + (ch << 10) + (h << 5) + w0);
    }
    #pragma unroll
    for (int it = 0; it < 3; ++it) {
        int v = it * 256 + threadIdx.x;
        int w0 = w0a[it];
        float4 out;
        out.x = (ld[it] && w0 + 0 >= cs && w0 + 0 < cs + GG) ? xv[it].x : 0.f;
        out.y = (ld[it] && w0 + 1 >= cs && w0 + 1 < cs + GG) ? xv[it].y : 0.f;
        out.z = (ld[it] && w0 + 2 >= cs && w0 + 2 < cs + GG) ? xv[it].z : 0.f;
        out.w = (ld[it] && w0 + 3 >= cs && w0 + 3 < cs + GG) ? xv[it].w : 0.f;
        __stcs((float4*)(fb + ((size_t)v << 2)), out);   // streaming: never re-read
    }

    // ---------- patch phase: 192 float4/sample, threads 0..191 ----------
    // Columns j0..j0+3 are contiguous in the patch; gather 4 scalars from x
    // (L1/L2 hits: the full phase just touched these lines).
    if (threadIdx.x < 192) {
        float* pb = patch + (size_t)b * PATCH_PER_B;
        int e4  = threadIdx.x;          // float4 index [0,192)
        int ch  = e4 >> 6;              // 64 float4 per channel (256 floats)
        int rem = e4 & 63;
        int i   = rem >> 2;             // patch row [0,16)
        int j0  = (rem & 3) << 2;       // first patch col of this float4
        int row = rs + i;
        float4 out = make_float4(0.f, 0.f, 0.f, 0.f);
        if (row >= 0 && row < 32) {
            const float* xr = xb + (ch << 10) + (row << 5);
            int c0 = cs + j0;
            if (c0 + 0 >= 0 && c0 + 0 < 32) out.x = xr[c0 + 0];
            if (c0 + 1 >= 0 && c0 + 1 < 32) out.y = xr[c0 + 1];
            if (c0 + 2 >= 0 && c0 + 2 < 32) out.z = xr[c0 + 2];
            if (c0 + 3 >= 0 && c0 + 3 < 32) out.w = xr[c0 + 3];
        }
        __stcs((float4*)(pb + ((size_t)e4 << 2)), out);
    }
}

extern "C" void kernel_launch(void* const* d_in, const int* in_sizes, int n_in,
                              void* d_out, int out_size)
{
    const float* x = (const float*)d_in[0];   // [16384,3,32,32]
    const float* l = (const float*)d_in[1];   // [16384,2]
    float* full  = (float*)d_out;
    float* patch = (float*)d_out + (size_t)BB * FULL_PER_B;
    retina_kernel<<<BB, 256>>>(x, l, full, patch);
}

// round 15
// speedup vs baseline: 1.0061x; 1.0006x over previous
#include <cuda_runtime.h>

// Retina glimpse: x [B=16384, C=3, 32, 32] f32, l [B,2] f32 in [-1,1].
// Outputs concatenated into d_out:
//   full  [B,3,32,32] : x masked to the valid part of the 16x16 window, else 0
//   patch [B,3,16,16] : gathered window, 0 where out of [0,32) bounds
//
// FINAL. Best-measured configuration (kernel 51.6-53.1us, wall 57.34us best).
// HBM-roofline-bound: 283 MB compulsory traffic at the ~5.3-5.5 TB/s mixed
// read/write DRAM ceiling, verified invariant across 13 structural variants
// (scalar/128b/256b stores, cp.async.bulk TMA, cache policies, smem staging,
// dependency splitting, store ordering, 2x MLP, warp specialization, block
// shapes, persistent CTAs). L1/L2/issue/occupancy unsaturated in every
// profile; remaining wall variance is run-to-run noise.

#define BB 16384
#define CC 3
#define HH 32
#define GG 16
#define FULL_PER_B (CC*HH*HH)   // 3072 floats
#define PATCH_PER_B (CC*GG*GG)  // 768 floats

__global__ __launch_bounds__(256) void retina_kernel(
    const float* __restrict__ x,
    const float* __restrict__ l,
    float* __restrict__ full,
    float* __restrict__ patch)
{
    const int b = blockIdx.x;

    // Every thread computes the window corner itself; l loads are same-line
    // L1 broadcasts. No smem, no barrier.
    float l0 = fminf(fmaxf(__ldg(&l[2 * b + 0]), -1.0f), 1.0f);
    float l1 = fminf(fmaxf(__ldg(&l[2 * b + 1]), -1.0f), 1.0f);
    const int rs = (int)(0.5f * ((l0 + 1.0f) * 32.0f)) - GG / 2;
    const int cs = (int)(0.5f * ((l1 + 1.0f) * 32.0f)) - GG / 2;

    const float* xb = x + (size_t)b * FULL_PER_B;
    float* fb = full + (size_t)b * FULL_PER_B;

    // ---------- full phase: 768 float4/sample, 3 per thread ----------
    // Issue all (predicated) loads first, then all stores.
    float4 xv[3];
    int  w0a[3];
    bool ld[3];
    #pragma unroll
    for (int it = 0; it < 3; ++it) {
        int v = it * 256 + threadIdx.x;     // [0,768)
        int ch  = v >> 8;
        int rem = v & 255;
        int h   = rem >> 3;
        int w0  = (rem & 7) << 2;
        w0a[it] = w0;
        bool rowin = (h >= rs) && (h < rs + GG);
        ld[it] = rowin && (w0 + 3 >= cs) && (w0 <= cs + GG - 1);
        xv[it] = make_float4(0.f, 0.f, 0.f, 0.f);
        if (ld[it])
            xv[it] = *(const float4*)(xb + (ch << 10) + (h << 5) + w0);
    }
    #pragma unroll
    for (int it = 0; it < 3; ++it) {
        int v = it * 256 + threadIdx.x;
        int w0 = w0a[it];
        float4 out;
        out.x = (ld[it] && w0 + 0 >= cs && w0 + 0 < cs + GG) ? xv[it].x : 0.f;
        out.y = (ld[it] && w0 + 1 >= cs && w0 + 1 < cs + GG) ? xv[it].y : 0.f;
        out.z = (ld[it] && w0 + 2 >= cs && w0 + 2 < cs + GG) ? xv[it].z : 0.f;
        out.w = (ld[it] && w0 + 3 >= cs && w0 + 3 < cs + GG) ? xv[it].w : 0.f;
        __stcs((float4*)(fb + ((size_t)v << 2)), out);   // streaming: never re-read
    }

    // ---------- patch phase: 192 float4/sample, threads 0..191 ----------
    // Columns j0..j0+3 are contiguous in the patch; gather 4 scalars from x
    // (L1/L2 hits: the full phase just touched these lines).
    if (threadIdx.x < 192) {
        float* pb = patch + (size_t)b * PATCH_PER_B;
        int e4  = threadIdx.x;          // float4 index [0,192)
        int ch  = e4 >> 6;              // 64 float4 per channel (256 floats)
        int rem = e4 & 63;
        int i   = rem >> 2;             // patch row [0,16)
        int j0  = (rem & 3) << 2;       // first patch col of this float4
        int row = rs + i;
        float4 out = make_float4(0.f, 0.f, 0.f, 0.f);
        if (row >= 0 && row < 32) {
            const float* xr = xb + (ch << 10) + (row << 5);
            int c0 = cs + j0;
            if (c0 + 0 >= 0 && c0 + 0 < 32) out.x = xr[c0 + 0];
            if (c0 + 1 >= 0 && c0 + 1 < 32) out.y = xr[c0 + 1];
            if (c0 + 2 >= 0 && c0 + 2 < 32) out.z = xr[c0 + 2];
            if (c0 + 3 >= 0 && c0 + 3 < 32) out.w = xr[c0 + 3];
        }
        __stcs((float4*)(pb + ((size_t)e4 << 2)), out);
    }
}

extern "C" void kernel_launch(void* const* d_in, const int* in_sizes, int n_in,
                              void* d_out, int out_size)
{
    const float* x = (const float*)d_in[0];   // [16384,3,32,32]
    const float* l = (const float*)d_in[1];   // [16384,2]
    float* full  = (float*)d_out;
    float* patch = (float*)d_out + (size_t)BB * FULL_PER_B;
    retina_kernel<<<BB, 256>>>(x, l, full, patch);
}